// round 7
// baseline (speedup 1.0000x reference)
#include <cuda_runtime.h>
#include <cuda_bf16.h>
#include <stdint.h>

#define GN 512
#define GW 332
#define GH 324
#define GHW (GW * GH)
#define GC 120
#define TSX 16
#define TSY 4
#define NROWS 81       // GH / TSY
#define CUT 25.0f      // 5-sigma: exp(-12.5) ~ 3.7e-6

// packed compact gaussian params (valid only, ORIGINAL index order)
__device__ float4 g_pk1[GN];            // gx, gy, c00, c11
__device__ float4 g_pk2[GN];            // op, depth, sid (float bits), rx
__device__ int    g_cnt;
__device__ int    g_rowcnt[NROWS];
__device__ float4 g_row1[NROWS][GN];    // per-row depth-ordered packed params
__device__ float4 g_row2[NROWS][GN];

static __device__ __forceinline__ unsigned order_float(float f) {
    unsigned u = __float_as_uint(f);
    return (u & 0x80000000u) ? ~u : (u | 0x80000000u);
}

// ---------------------------------------------------------------------------
// Kernel 1: project, validity, cinv, ballot-compact valid set (index order).
// One block, 512 threads. No sort here (sorting happens per-row in parallel).
// ---------------------------------------------------------------------------
__global__ __launch_bounds__(GN) void prep_kernel(
    const float* __restrict__ pos,     // [N,3]
    const float* __restrict__ scales,  // [N,3]
    const float* __restrict__ ops,     // [N]
    const float* __restrict__ K,       // [3,3]
    const float* __restrict__ E)       // [4,4]
{
    __shared__ int s_wcnt[16];
    const int i = threadIdx.x;

    float p0 = pos[3 * i + 0], p1 = pos[3 * i + 1], p2 = pos[3 * i + 2];
    float cx = E[0] * p0 + E[1] * p1 + E[2]  * p2 + E[3];
    float cy = E[4] * p0 + E[5] * p1 + E[6]  * p2 + E[7];
    float cz = E[8] * p0 + E[9] * p1 + E[10] * p2 + E[11];
    float prx = K[0] * cx + K[1] * cy + K[2] * cz;
    float pry = K[3] * cx + K[4] * cy + K[5] * cz;
    float prz = K[6] * cx + K[7] * cy + K[8] * cz;
    float sx = prx / (prz + 1e-6f);
    float sy = pry / (prz + 1e-6f);
    float d  = cz;

    bool valid = (d > 0.01f) && (d < 100.0f) &&
                 (sx > -100.0f) && (sx < (float)GW + 100.0f) &&
                 (sy > -100.0f) && (sy < (float)GH + 100.0f);

    float s0 = scales[3 * i + 0], s1 = scales[3 * i + 1];
    float c00 = 1.0f / (s0 * s0 + 1e-4f);
    float c11 = 1.0f / (s1 * s1 + 1e-4f);

    unsigned bm = __ballot_sync(0xffffffffu, valid);
    int lane = i & 31, w = i >> 5;
    if (lane == 0) s_wcnt[w] = __popc(bm);
    __syncthreads();
    int woff = 0;
#pragma unroll
    for (int ww = 0; ww < 16; ww++)
        if (ww < w) woff += s_wcnt[ww];
    if (valid) {
        int p = woff + __popc(bm & ((1u << lane) - 1u));
        g_pk1[p] = make_float4(sx, sy, c00, c11);
        g_pk2[p] = make_float4(ops[i], d, __int_as_float(i), sqrtf(CUT / c00));
    }
    if (i == 0) {
        int tot = 0;
#pragma unroll
        for (int ww = 0; ww < 16; ww++) tot += s_wcnt[ww];
        g_cnt = tot;
    }
}

// ---------------------------------------------------------------------------
// Kernel 1b: per-row cull + LOCAL depth sort. One block per tile row.
// Cull preserves compact (=original index) order; local bitonic sort by
// (depth, slot) => exactly the stable argsort restricted to this row.
// ---------------------------------------------------------------------------
__global__ __launch_bounds__(256) void bin_kernel()
{
    __shared__ unsigned long long s_key[GN];
    __shared__ int s_idx[GN];
    __shared__ int s_cnt, s_wcnt[8];

    const int tid = threadIdx.x;
    const int row = blockIdx.x;
    if (tid == 0) s_cnt = 0;
    const int M = g_cnt;
    const float ry0 = (float)(row * TSY);
    const float ry1 = (float)(row * TSY + TSY - 1);
    __syncthreads();

    // Order-preserving cull by row span.
    for (int base = 0; base < M; base += 256) {
        int li = base + tid;
        bool keep = false;
        float dep = 0.f;
        if (li < M) {
            float4 f1 = g_pk1[li];
            dep = g_pk2[li].y;
            float ry = sqrtf(CUT / f1.w);
            keep = (f1.y + ry >= ry0) && (f1.y - ry <= ry1);
        }
        unsigned bm = __ballot_sync(0xffffffffu, keep);
        int lane = tid & 31, w = tid >> 5;
        if (lane == 0) s_wcnt[w] = __popc(bm);
        __syncthreads();
        int woff = 0;
#pragma unroll
        for (int ww = 0; ww < 8; ww++)
            if (ww < w) woff += s_wcnt[ww];
        if (keep) {
            int p = s_cnt + woff + __popc(bm & ((1u << lane) - 1u));
            s_idx[p] = li;
            s_key[p] = ((unsigned long long)order_float(dep) << 32) | (unsigned)p;
        }
        __syncthreads();
        if (tid == 0) {
            int tt = 0;
#pragma unroll
            for (int ww = 0; ww < 8; ww++) tt += s_wcnt[ww];
            s_cnt += tt;
        }
        __syncthreads();
    }
    const int cnt = s_cnt;

    // Pad to next power of two.
    int p2 = 1;
    while (p2 < cnt) p2 <<= 1;
    for (int p = cnt + tid; p < p2; p += 256)
        s_key[p] = 0xffffffffffffffffull;
    __syncthreads();

    // Bitonic sort of p2 keys with 256 threads (p2/2 <= 256 pairs).
    for (int k = 2; k <= p2; k <<= 1) {
        for (int j = k >> 1; j > 0; j >>= 1) {
            if (tid < (p2 >> 1)) {
                int i = ((tid & ~(j - 1)) << 1) | (tid & (j - 1));
                int ixj = i | j;
                unsigned long long a = s_key[i], b = s_key[ixj];
                bool asc = ((i & k) == 0);
                if ((a > b) == asc) { s_key[i] = b; s_key[ixj] = a; }
            }
            __syncthreads();
        }
    }

    // Write depth-ordered packed params for this row (coalesced-ish gather).
    for (int p = tid; p < cnt; p += 256) {
        int ci = s_idx[(int)(s_key[p] & 0xffffffffu)];
        g_row1[row][p] = g_pk1[ci];
        g_row2[row][p] = g_pk2[ci];
    }
    if (tid == 0) g_rowcnt[row] = cnt;
}

// ---------------------------------------------------------------------------
// Kernel 2: per-tile x-cull (row bin) + branchless depth-ordered compositing.
// Block = 256 threads = 64 pixels (16x4 tile) x 4 channel groups.
// ---------------------------------------------------------------------------
__global__ __launch_bounds__(256, 3) void render_kernel(
    const float* __restrict__ spec,   // [N, C]
    const float* __restrict__ tone,   // [C]
    float* __restrict__ out)          // [C*HW + HW + HW]
{
    __shared__ float4 s1[GN];         // gx, gy, c00, c11
    __shared__ float4 s2[GN];         // op, depth, sid, rx
    __shared__ float  s_tone[GC];
    __shared__ int    s_cnt, s_wcnt[8];

    const int tid = threadIdx.x;
    if (tid < GC) s_tone[tid] = tone[tid];
    if (tid == 0) s_cnt = 0;

    const int row  = blockIdx.y;
    const int Mrow = g_rowcnt[row];
    const int x0 = blockIdx.x * TSX, y0 = row * TSY;
    const float fx0 = (float)x0, fx1 = (float)(x0 + TSX - 1);
    __syncthreads();

    // Order-preserving x-cull from this row's packed list (chunks of 256).
    for (int base = 0; base < Mrow; base += 256) {
        int li = base + tid;
        bool keep = false;
        float4 f1, f2;
        if (li < Mrow) {
            f1 = g_row1[row][li];
            f2 = g_row2[row][li];
            keep = (f1.x + f2.w >= fx0) && (f1.x - f2.w <= fx1);
        }
        unsigned bm = __ballot_sync(0xffffffffu, keep);
        int lane = tid & 31, w = tid >> 5;
        if (lane == 0) s_wcnt[w] = __popc(bm);
        __syncthreads();
        int woff = 0;
#pragma unroll
        for (int ww = 0; ww < 8; ww++)
            if (ww < w) woff += s_wcnt[ww];
        if (keep) {
            int p = s_cnt + woff + __popc(bm & ((1u << lane) - 1u));
            s1[p] = f1;
            s2[p] = f2;
        }
        __syncthreads();
        if (tid == 0) {
            int tt = 0;
#pragma unroll
            for (int ww = 0; ww < 8; ww++) tt += s_wcnt[ww];
            s_cnt += tt;
        }
        __syncthreads();
    }
    const int cnt = s_cnt;

    const int cg  = tid >> 6;          // channel group 0..3 (warp-uniform)
    const int pix = tid & 63;          // pixel within 16x4 tile
    const int px  = x0 + (pix & 15);
    const int py  = y0 + (pix >> 4);
    const float fpx = (float)px, fpy = (float)py;
    const int cbase = cg * 32;         // 0,32,64,96

    float A = 0.0f, D = 0.0f;
    float acc[32];
#pragma unroll
    for (int c = 0; c < 32; c++) acc[c] = 0.0f;

    // Branchless depth-ordered compositing (uniform LDS.128 broadcasts;
    // exp underflow -> 0 for far gaussians).
    for (int k = 0; k < cnt; k++) {
        float4 P1 = s1[k];
        float4 P2 = s2[k];
        float dx = fpx - P1.x;
        float dy = fpy - P1.y;
        float m  = dx * dx * P1.z + dy * dy * P1.w;
        float alpha = P2.x * __expf(-0.5f * m) * (1.0f - A);
        A += alpha;
        D += P2.y * alpha;
        const float4* sp = (const float4*)(spec + (size_t)__float_as_int(P2.z) * GC + cbase);
        if (cg < 3) {
#pragma unroll
            for (int q = 0; q < 8; q++) {
                float4 v = __ldg(sp + q);
                acc[4 * q + 0] += alpha * v.x;
                acc[4 * q + 1] += alpha * v.y;
                acc[4 * q + 2] += alpha * v.z;
                acc[4 * q + 3] += alpha * v.w;
            }
        } else {
#pragma unroll
            for (int q = 0; q < 6; q++) {
                float4 v = __ldg(sp + q);
                acc[4 * q + 0] += alpha * v.x;
                acc[4 * q + 1] += alpha * v.y;
                acc[4 * q + 2] += alpha * v.z;
                acc[4 * q + 3] += alpha * v.w;
            }
        }
    }

    if (px < GW) {   // py always < GH (324 = 81*4)
        const int p = py * GW + px;
        const float bg = 1.0f - A;   // BG = 1.0
        const int nch = (cg < 3) ? 32 : 24;
#pragma unroll 8
        for (int c = 0; c < nch; c++)
            out[(size_t)(cbase + c) * GHW + p] = (acc[c] + bg) * s_tone[cbase + c];
        if (cg == 0) {
            out[(size_t)GC * GHW + p] = D;              // depth image
            out[(size_t)GC * GHW + GHW + p] = A;        // A_final
        }
    }
}

// ---------------------------------------------------------------------------
// Inputs (metadata order): positions[N,3], rotations[N,4](unused), scales[N,3],
// opacities[N], spectral_features[N,C], tone_mapping[C], intrinsics[3,3],
// extrinsics[4,4]. Output: concat(spectral[C,H,W], depth[H,W], A[H,W]) fp32.
// ---------------------------------------------------------------------------
extern "C" void kernel_launch(void* const* d_in, const int* in_sizes, int n_in,
                              void* d_out, int out_size)
{
    const float* positions  = (const float*)d_in[0];
    const float* scales     = (const float*)d_in[2];
    const float* opacities  = (const float*)d_in[3];
    const float* spectral   = (const float*)d_in[4];
    const float* tone       = (const float*)d_in[5];
    const float* intr       = (const float*)d_in[6];
    const float* extr       = (const float*)d_in[7];
    float* out = (float*)d_out;

    prep_kernel<<<1, GN>>>(positions, scales, opacities, intr, extr);
    bin_kernel<<<NROWS, 256>>>();

    dim3 grid((GW + TSX - 1) / TSX, NROWS);
    render_kernel<<<grid, 256>>>(spectral, tone, out);
}

// round 9
// speedup vs baseline: 1.6682x; 1.6682x over previous
#include <cuda_runtime.h>
#include <cuda_bf16.h>
#include <stdint.h>

#define GN 512
#define GW 332
#define GH 324
#define GHW (GW * GH)
#define GC 120
#define TSX 16
#define TSY 4
#define CUT 25.0f      // 5-sigma: exp(-12.5) ~ 3.7e-6

static __device__ __forceinline__ unsigned order_float(float f) {
    unsigned u = __float_as_uint(f);
    return (u & 0x80000000u) ? ~u : (u | 0x80000000u);
}

// ---------------------------------------------------------------------------
// Single fused kernel. Block = 256 threads = 64 pixels (16x4 tile) x 4
// channel groups. Each block:
//   1) projects all 512 gaussians (2 per thread, index order preserved)
//   2) ballot-compacts those overlapping its tile (stable, index order)
//   3) bitonic-sorts the culled list by (depth, slot)  == stable argsort
//   4) permutes params into depth order in smem
//   5) branchless depth-ordered alpha compositing
// ---------------------------------------------------------------------------
__global__ __launch_bounds__(256, 3) void fused_kernel(
    const float* __restrict__ pos,     // [N,3]
    const float* __restrict__ scales,  // [N,3]
    const float* __restrict__ ops,     // [N]
    const float* __restrict__ spec,    // [N,C]
    const float* __restrict__ tone,    // [C]
    const float* __restrict__ K,       // [3,3]
    const float* __restrict__ E,       // [4,4]
    float* __restrict__ out)           // [C*HW + HW + HW]
{
    __shared__ float4 a1[GN], a2[GN];           // staged (index order)
    __shared__ float4 b1[GN], b2[GN];           // depth-sorted
    __shared__ unsigned long long s_key[GN];
    __shared__ float s_tone[GC];
    __shared__ int   s_cnt, s_wcnt[8];

    const int tid = threadIdx.x;
    if (tid < GC) s_tone[tid] = __ldg(tone + tid);
    if (tid == 0) s_cnt = 0;

    const int x0 = blockIdx.x * TSX, y0 = blockIdx.y * TSY;
    const float fx0 = (float)x0, fx1 = (float)(x0 + TSX - 1);
    const float fy0 = (float)y0, fy1 = (float)(y0 + TSY - 1);

    // Camera matrices (uniform broadcast loads, L1/L2 cached).
    float E0 = __ldg(E + 0), E1 = __ldg(E + 1), E2  = __ldg(E + 2),  E3  = __ldg(E + 3);
    float E4 = __ldg(E + 4), E5 = __ldg(E + 5), E6  = __ldg(E + 6),  E7  = __ldg(E + 7);
    float E8 = __ldg(E + 8), E9 = __ldg(E + 9), E10 = __ldg(E + 10), E11 = __ldg(E + 11);
    float K0 = __ldg(K + 0), K1 = __ldg(K + 1), K2 = __ldg(K + 2);
    float K3 = __ldg(K + 3), K4 = __ldg(K + 4), K5 = __ldg(K + 5);
    float K6 = __ldg(K + 6), K7 = __ldg(K + 7), K8 = __ldg(K + 8);
    __syncthreads();

    // ---- Project + cull, 2 chunks of 256 (index order preserved) ----
#pragma unroll
    for (int c = 0; c < 2; c++) {
        const int i = c * 256 + tid;
        float p0 = __ldg(pos + 3 * i + 0), p1 = __ldg(pos + 3 * i + 1), p2 = __ldg(pos + 3 * i + 2);
        float cx = E0 * p0 + E1 * p1 + E2  * p2 + E3;
        float cy = E4 * p0 + E5 * p1 + E6  * p2 + E7;
        float cz = E8 * p0 + E9 * p1 + E10 * p2 + E11;
        float prx = K0 * cx + K1 * cy + K2 * cz;
        float pry = K3 * cx + K4 * cy + K5 * cz;
        float prz = K6 * cx + K7 * cy + K8 * cz;
        float sx = prx / (prz + 1e-6f);
        float sy = pry / (prz + 1e-6f);
        float d  = cz;

        bool valid = (d > 0.01f) && (d < 100.0f) &&
                     (sx > -100.0f) && (sx < (float)GW + 100.0f) &&
                     (sy > -100.0f) && (sy < (float)GH + 100.0f);

        float s0 = __ldg(scales + 3 * i + 0), s1v = __ldg(scales + 3 * i + 1);
        float c00 = 1.0f / (s0 * s0 + 1e-4f);
        float c11 = 1.0f / (s1v * s1v + 1e-4f);
        float rx = sqrtf(CUT / c00);
        float ry = sqrtf(CUT / c11);

        bool keep = valid &&
                    (sx + rx >= fx0) && (sx - rx <= fx1) &&
                    (sy + ry >= fy0) && (sy - ry <= fy1);

        unsigned bm = __ballot_sync(0xffffffffu, keep);
        int lane = tid & 31, w = tid >> 5;
        if (lane == 0) s_wcnt[w] = __popc(bm);
        __syncthreads();
        int woff = 0;
#pragma unroll
        for (int ww = 0; ww < 8; ww++)
            if (ww < w) woff += s_wcnt[ww];
        if (keep) {
            int p = s_cnt + woff + __popc(bm & ((1u << lane) - 1u));
            a1[p] = make_float4(sx, sy, c00, c11);
            a2[p] = make_float4(__ldg(ops + i), d, __int_as_float(i), 0.0f);
            s_key[p] = ((unsigned long long)order_float(d) << 32) | (unsigned)p;
        }
        __syncthreads();
        if (tid == 0) {
            int tt = 0;
#pragma unroll
            for (int ww = 0; ww < 8; ww++) tt += s_wcnt[ww];
            s_cnt += tt;
        }
        __syncthreads();
    }
    const int cnt = s_cnt;

    // ---- Local bitonic sort by (depth, slot) ----
    int p2 = 1;
    while (p2 < cnt) p2 <<= 1;
    for (int p = cnt + tid; p < p2; p += 256)
        s_key[p] = 0xffffffffffffffffull;
    __syncthreads();
    for (int k = 2; k <= p2; k <<= 1) {
        for (int j = k >> 1; j > 0; j >>= 1) {
            if (tid < (p2 >> 1)) {
                int i = ((tid & ~(j - 1)) << 1) | (tid & (j - 1));
                int ixj = i | j;
                unsigned long long va = s_key[i], vb = s_key[ixj];
                bool asc = ((i & k) == 0);
                if ((va > vb) == asc) { s_key[i] = vb; s_key[ixj] = va; }
            }
            __syncthreads();
        }
    }

    // ---- Permute into depth order ----
    for (int p = tid; p < cnt; p += 256) {
        int slot = (int)(s_key[p] & 0xffffffffu);
        b1[p] = a1[slot];
        b2[p] = a2[slot];
    }
    __syncthreads();

    // ---- Compositing ----
    const int cg  = tid >> 6;          // channel group 0..3 (warp-uniform)
    const int pix = tid & 63;          // pixel within 16x4 tile
    const int px  = x0 + (pix & 15);
    const int py  = y0 + (pix >> 4);
    const float fpx = (float)px, fpy = (float)py;
    const int cbase = cg * 32;         // 0,32,64,96

    float A = 0.0f, D = 0.0f;
    float acc[32];
#pragma unroll
    for (int c = 0; c < 32; c++) acc[c] = 0.0f;

    for (int k = 0; k < cnt; k++) {
        float4 P1 = b1[k];
        float4 P2 = b2[k];
        float dx = fpx - P1.x;
        float dy = fpy - P1.y;
        float m  = dx * dx * P1.z + dy * dy * P1.w;
        float alpha = P2.x * __expf(-0.5f * m) * (1.0f - A);
        A += alpha;
        D += P2.y * alpha;
        const float4* sp = (const float4*)(spec + (size_t)__float_as_int(P2.z) * GC + cbase);
        if (cg < 3) {
#pragma unroll
            for (int q = 0; q < 8; q++) {
                float4 v = __ldg(sp + q);
                acc[4 * q + 0] += alpha * v.x;
                acc[4 * q + 1] += alpha * v.y;
                acc[4 * q + 2] += alpha * v.z;
                acc[4 * q + 3] += alpha * v.w;
            }
        } else {
#pragma unroll
            for (int q = 0; q < 6; q++) {
                float4 v = __ldg(sp + q);
                acc[4 * q + 0] += alpha * v.x;
                acc[4 * q + 1] += alpha * v.y;
                acc[4 * q + 2] += alpha * v.z;
                acc[4 * q + 3] += alpha * v.w;
            }
        }
    }

    if (px < GW) {   // py always < GH (324 = 81*4)
        const int p = py * GW + px;
        const float bg = 1.0f - A;   // BG = 1.0
        const int nch = (cg < 3) ? 32 : 24;
#pragma unroll 8
        for (int c = 0; c < nch; c++)
            out[(size_t)(cbase + c) * GHW + p] = (acc[c] + bg) * s_tone[cbase + c];
        if (cg == 0) {
            out[(size_t)GC * GHW + p] = D;              // depth image
            out[(size_t)GC * GHW + GHW + p] = A;        // A_final
        }
    }
}

// ---------------------------------------------------------------------------
// Inputs (metadata order): positions[N,3], rotations[N,4](unused), scales[N,3],
// opacities[N], spectral_features[N,C], tone_mapping[C], intrinsics[3,3],
// extrinsics[4,4]. Output: concat(spectral[C,H,W], depth[H,W], A[H,W]) fp32.
// ---------------------------------------------------------------------------
extern "C" void kernel_launch(void* const* d_in, const int* in_sizes, int n_in,
                              void* d_out, int out_size)
{
    const float* positions  = (const float*)d_in[0];
    const float* scales     = (const float*)d_in[2];
    const float* opacities  = (const float*)d_in[3];
    const float* spectral   = (const float*)d_in[4];
    const float* tone       = (const float*)d_in[5];
    const float* intr       = (const float*)d_in[6];
    const float* extr       = (const float*)d_in[7];
    float* out = (float*)d_out;

    dim3 grid((GW + TSX - 1) / TSX, (GH + TSY - 1) / TSY);
    fused_kernel<<<grid, 256>>>(positions, scales, opacities, spectral, tone,
                                intr, extr, out);
}

// round 10
// speedup vs baseline: 1.7466x; 1.0470x over previous
#include <cuda_runtime.h>
#include <cuda_bf16.h>
#include <stdint.h>

#define GN 512
#define GW 332
#define GH 324
#define GHW (GW * GH)
#define GC 120
#define TSX 16
#define TSY 4
#define CUT 25.0f      // 5-sigma: exp(-12.5) ~ 3.7e-6

static __device__ __forceinline__ unsigned order_float(float f) {
    unsigned u = __float_as_uint(f);
    return (u & 0x80000000u) ? ~u : (u | 0x80000000u);
}

// ---------------------------------------------------------------------------
// Single fused kernel. Block = 256 threads = 64 pixels (16x4 tile) x 4
// channel groups. Each block:
//   1) projects all 512 gaussians (2 per thread, index order preserved)
//   2) ballot-compacts those whose 5-sigma ELLIPSE reaches the tile
//      (exact min-mahalanobis over the tile rect; tighter than bbox)
//   3) bitonic-sorts the culled list by (depth, slot)  == stable argsort
//   4) permutes params into depth order in smem
//   5) branchless depth-ordered alpha compositing, with per-warp skip of
//      the spectral FMA block when every lane's alpha is negligible
// ---------------------------------------------------------------------------
__global__ __launch_bounds__(256, 3) void fused_kernel(
    const float* __restrict__ pos,     // [N,3]
    const float* __restrict__ scales,  // [N,3]
    const float* __restrict__ ops,     // [N]
    const float* __restrict__ spec,    // [N,C]
    const float* __restrict__ tone,    // [C]
    const float* __restrict__ K,       // [3,3]
    const float* __restrict__ E,       // [4,4]
    float* __restrict__ out)           // [C*HW + HW + HW]
{
    __shared__ float4 a1[GN], a2[GN];           // staged (index order)
    __shared__ float4 b1[GN], b2[GN];           // depth-sorted
    __shared__ unsigned long long s_key[GN];
    __shared__ float s_tone[GC];
    __shared__ int   s_cnt, s_wcnt[8];

    const int tid = threadIdx.x;
    if (tid < GC) s_tone[tid] = __ldg(tone + tid);
    if (tid == 0) s_cnt = 0;

    const int x0 = blockIdx.x * TSX, y0 = blockIdx.y * TSY;
    const float fx0 = (float)x0, fx1 = (float)(x0 + TSX - 1);
    const float fy0 = (float)y0, fy1 = (float)(y0 + TSY - 1);

    // Camera matrices (uniform broadcast loads, L1/L2 cached).
    float E0 = __ldg(E + 0), E1 = __ldg(E + 1), E2  = __ldg(E + 2),  E3  = __ldg(E + 3);
    float E4 = __ldg(E + 4), E5 = __ldg(E + 5), E6  = __ldg(E + 6),  E7  = __ldg(E + 7);
    float E8 = __ldg(E + 8), E9 = __ldg(E + 9), E10 = __ldg(E + 10), E11 = __ldg(E + 11);
    float K0 = __ldg(K + 0), K1 = __ldg(K + 1), K2 = __ldg(K + 2);
    float K3 = __ldg(K + 3), K4 = __ldg(K + 4), K5 = __ldg(K + 5);
    float K6 = __ldg(K + 6), K7 = __ldg(K + 7), K8 = __ldg(K + 8);
    __syncthreads();

    // ---- Project + ellipse cull, 2 chunks of 256 (index order preserved) ----
#pragma unroll
    for (int c = 0; c < 2; c++) {
        const int i = c * 256 + tid;
        float p0 = __ldg(pos + 3 * i + 0), p1 = __ldg(pos + 3 * i + 1), p2 = __ldg(pos + 3 * i + 2);
        float cx = E0 * p0 + E1 * p1 + E2  * p2 + E3;
        float cy = E4 * p0 + E5 * p1 + E6  * p2 + E7;
        float cz = E8 * p0 + E9 * p1 + E10 * p2 + E11;
        float prx = K0 * cx + K1 * cy + K2 * cz;
        float pry = K3 * cx + K4 * cy + K5 * cz;
        float prz = K6 * cx + K7 * cy + K8 * cz;
        float sx = prx / (prz + 1e-6f);
        float sy = pry / (prz + 1e-6f);
        float d  = cz;

        bool valid = (d > 0.01f) && (d < 100.0f) &&
                     (sx > -100.0f) && (sx < (float)GW + 100.0f) &&
                     (sy > -100.0f) && (sy < (float)GH + 100.0f);

        float s0 = __ldg(scales + 3 * i + 0), s1v = __ldg(scales + 3 * i + 1);
        float c00 = 1.0f / (s0 * s0 + 1e-4f);
        float c11 = 1.0f / (s1v * s1v + 1e-4f);

        // Exact min mahalanobis over the tile rect: clamp center to rect.
        float nx = fminf(fmaxf(sx, fx0), fx1);
        float ny = fminf(fmaxf(sy, fy0), fy1);
        float ddx = sx - nx, ddy = sy - ny;
        float m_min = ddx * ddx * c00 + ddy * ddy * c11;

        bool keep = valid && (m_min < CUT);

        unsigned bm = __ballot_sync(0xffffffffu, keep);
        int lane = tid & 31, w = tid >> 5;
        if (lane == 0) s_wcnt[w] = __popc(bm);
        __syncthreads();
        int woff = 0;
#pragma unroll
        for (int ww = 0; ww < 8; ww++)
            if (ww < w) woff += s_wcnt[ww];
        if (keep) {
            int p = s_cnt + woff + __popc(bm & ((1u << lane) - 1u));
            a1[p] = make_float4(sx, sy, c00, c11);
            a2[p] = make_float4(__ldg(ops + i), d, __int_as_float(i), 0.0f);
            s_key[p] = ((unsigned long long)order_float(d) << 32) | (unsigned)p;
        }
        __syncthreads();
        if (tid == 0) {
            int tt = 0;
#pragma unroll
            for (int ww = 0; ww < 8; ww++) tt += s_wcnt[ww];
            s_cnt += tt;
        }
        __syncthreads();
    }
    const int cnt = s_cnt;

    // ---- Local bitonic sort by (depth, slot) ----
    int p2 = 1;
    while (p2 < cnt) p2 <<= 1;
    for (int p = cnt + tid; p < p2; p += 256)
        s_key[p] = 0xffffffffffffffffull;
    __syncthreads();
    for (int k = 2; k <= p2; k <<= 1) {
        for (int j = k >> 1; j > 0; j >>= 1) {
            if (tid < (p2 >> 1)) {
                int i = ((tid & ~(j - 1)) << 1) | (tid & (j - 1));
                int ixj = i | j;
                unsigned long long va = s_key[i], vb = s_key[ixj];
                bool asc = ((i & k) == 0);
                if ((va > vb) == asc) { s_key[i] = vb; s_key[ixj] = va; }
            }
            __syncthreads();
        }
    }

    // ---- Permute into depth order ----
    for (int p = tid; p < cnt; p += 256) {
        int slot = (int)(s_key[p] & 0xffffffffu);
        b1[p] = a1[slot];
        b2[p] = a2[slot];
    }
    __syncthreads();

    // ---- Compositing ----
    const int cg  = tid >> 6;          // channel group 0..3 (warp-uniform)
    const int pix = tid & 63;          // pixel within 16x4 tile
    const int px  = x0 + (pix & 15);
    const int py  = y0 + (pix >> 4);
    const float fpx = (float)px, fpy = (float)py;
    const int cbase = cg * 32;         // 0,32,64,96

    float A = 0.0f, D = 0.0f;
    float acc[32];
#pragma unroll
    for (int c = 0; c < 32; c++) acc[c] = 0.0f;

    for (int k = 0; k < cnt; k++) {
        float4 P1 = b1[k];
        float4 P2 = b2[k];
        float dx = fpx - P1.x;
        float dy = fpy - P1.y;
        float m  = dx * dx * P1.z + dy * dy * P1.w;
        float alpha = P2.x * __expf(-0.5f * m) * (1.0f - A);
        A += alpha;
        D += P2.y * alpha;
        // Skip the spectral FMA block if every lane's alpha is negligible
        // (contribution <= ~1e-7 each; aggregate error << 1e-3 tolerance).
        if (!__any_sync(0xffffffffu, alpha > 1e-7f)) continue;
        const float4* sp = (const float4*)(spec + (size_t)__float_as_int(P2.z) * GC + cbase);
        if (cg < 3) {
#pragma unroll
            for (int q = 0; q < 8; q++) {
                float4 v = __ldg(sp + q);
                acc[4 * q + 0] += alpha * v.x;
                acc[4 * q + 1] += alpha * v.y;
                acc[4 * q + 2] += alpha * v.z;
                acc[4 * q + 3] += alpha * v.w;
            }
        } else {
#pragma unroll
            for (int q = 0; q < 6; q++) {
                float4 v = __ldg(sp + q);
                acc[4 * q + 0] += alpha * v.x;
                acc[4 * q + 1] += alpha * v.y;
                acc[4 * q + 2] += alpha * v.z;
                acc[4 * q + 3] += alpha * v.w;
            }
        }
    }

    if (px < GW) {   // py always < GH (324 = 81*4)
        const int p = py * GW + px;
        const float bg = 1.0f - A;   // BG = 1.0
        const int nch = (cg < 3) ? 32 : 24;
#pragma unroll 8
        for (int c = 0; c < nch; c++)
            out[(size_t)(cbase + c) * GHW + p] = (acc[c] + bg) * s_tone[cbase + c];
        if (cg == 0) {
            out[(size_t)GC * GHW + p] = D;              // depth image
            out[(size_t)GC * GHW + GHW + p] = A;        // A_final
        }
    }
}

// ---------------------------------------------------------------------------
// Inputs (metadata order): positions[N,3], rotations[N,4](unused), scales[N,3],
// opacities[N], spectral_features[N,C], tone_mapping[C], intrinsics[3,3],
// extrinsics[4,4]. Output: concat(spectral[C,H,W], depth[H,W], A[H,W]) fp32.
// ---------------------------------------------------------------------------
extern "C" void kernel_launch(void* const* d_in, const int* in_sizes, int n_in,
                              void* d_out, int out_size)
{
    const float* positions  = (const float*)d_in[0];
    const float* scales     = (const float*)d_in[2];
    const float* opacities  = (const float*)d_in[3];
    const float* spectral   = (const float*)d_in[4];
    const float* tone       = (const float*)d_in[5];
    const float* intr       = (const float*)d_in[6];
    const float* extr       = (const float*)d_in[7];
    float* out = (float*)d_out;

    dim3 grid((GW + TSX - 1) / TSX, (GH + TSY - 1) / TSY);
    fused_kernel<<<grid, 256>>>(positions, scales, opacities, spectral, tone,
                                intr, extr, out);
}